// round 1
// baseline (speedup 1.0000x reference)
#include <cuda_runtime.h>

#define H  128
#define W  256
#define HW 32768
#define C  64
#define FH 128      // cube face size

// ---------------- scratch (device globals; no allocation allowed) ----------------
__device__ float g_aux [4*C*HW];
__device__ float g_main[4*C*HW];
__device__ float g_maux[4*C*HW];
__device__ int   g_geo[HW];
__device__ float g_dx[HW];
__device__ float g_dy[HW];

// ---------------- packed f32x2 helpers (Blackwell) ----------------
typedef unsigned long long u64;
__device__ __forceinline__ u64 pack2(float a, float b) {
    u64 r; asm("mov.b64 %0, {%1, %2};" : "=l"(r) : "f"(a), "f"(b)); return r;
}
__device__ __forceinline__ void ffma2(u64& d, u64 a, u64 b) {
    asm("fma.rn.f32x2 %0, %1, %2, %0;" : "+l"(d) : "l"(a), "l"(b));
}
__device__ __forceinline__ float2 unpack2(u64 v) {
    float2 r; asm("mov.b64 {%0, %1}, %2;" : "=f"(r.x), "=f"(r.y) : "l"(v)); return r;
}

// ---------------- 1) per-pixel cube geometry ----------------
__global__ void geom_kernel() {
    int p = blockIdx.x * blockDim.x + threadIdx.x;
    if (p >= HW) return;
    int i = p >> 8;          // row   (H=128)
    int j = p & 255;         // col   (W=256)
    const float PI = 3.14159265358979323846f;
    float lat = (0.5f - (i + 0.5f) / 128.f) * PI;
    float lon = (2.f * (j + 0.5f) / 256.f - 1.f) * PI;
    float cl = cosf(lat);
    float vx = cl * sinf(lon);
    float vy = sinf(lat);
    float vz = cl * cosf(lon);
    float ax = fabsf(vx), ay = fabsf(vy), az = fabsf(vz);
    bool cond_z = (az >= ax) && (az >= ay);
    bool cond_x = (!cond_z) && (ax >= ay);
    int face;
    if (cond_z)      face = (vz > 0.f) ? 2 : 0;
    else if (cond_x) face = (vx > 0.f) ? 4 : 3;
    else             face = (vy > 0.f) ? 5 : 1;

    float den, a, bc;
    switch (face) {
        case 0: den = -vz; a = -vx / den; bc =  vy / den; break;  // back
        case 1: den = -vy; a =  vx / den; bc = -vz / den; break;  // down
        case 2: den =  vz; a =  vx / den; bc =  vy / den; break;  // front
        case 3: den = -vx; a =  vz / den; bc =  vy / den; break;  // left
        case 4: den =  vx; a = -vz / den; bc =  vy / den; break;  // right
        default:den =  vy; a =  vx / den; bc =  vz / den; break;  // up
    }
    float uu = fminf(fmaxf((a   + 1.f) * 0.5f * 127.f, 0.f), 127.f);
    float vv = fminf(fmaxf((1.f - bc ) * 0.5f * 127.f, 0.f), 127.f);
    int x0 = (int)floorf(uu);
    int y0 = (int)floorf(vv);
    int x1 = min(x0 + 1, 127);
    int y1 = min(y0 + 1, 127);
    g_geo[p] = face | (x0 << 3) | (y0 << 10) | (x1 << 17) | (y1 << 24);
    g_dx[p] = uu - (float)x0;
    g_dy[p] = vv - (float)y0;
}

// ---------------- 2) bilinear cube gather -> aux ----------------
__global__ __launch_bounds__(256) void gather_kernel(
    const float* __restrict__ fb, const float* __restrict__ fd,
    const float* __restrict__ ff, const float* __restrict__ fl,
    const float* __restrict__ fr, const float* __restrict__ fu)
{
    int idx = blockIdx.x * 256 + threadIdx.x;     // bc*HW + p
    int p  = idx & (HW - 1);
    int bc = idx >> 15;
    int geo = g_geo[p];
    int face = geo & 7;
    int x0 = (geo >> 3)  & 127;
    int y0 = (geo >> 10) & 127;
    int x1 = (geo >> 17) & 127;
    int y1 = (geo >> 24) & 127;
    float dx = g_dx[p], dy = g_dy[p];
    const float* fp;
    switch (face) {
        case 0: fp = fb; break;
        case 1: fp = fd; break;
        case 2: fp = ff; break;
        case 3: fp = fl; break;
        case 4: fp = fr; break;
        default: fp = fu; break;
    }
    fp += (size_t)bc * (FH * FH);
    float v00 = fp[y0 * FH + x0];
    float v01 = fp[y0 * FH + x1];
    float v10 = fp[y1 * FH + x0];
    float v11 = fp[y1 * FH + x1];
    float r = v00 * ((1.f - dx) * (1.f - dy))
            + v01 * (dx * (1.f - dy))
            + v10 * ((1.f - dx) * dy)
            + v11 * (dx * dy);
    g_aux[idx] = r;
}

// ---------------- 3) 3x3 conv + relu (shared weights), f32x2 packed ----------------
#define OCB 16
#define ICB 2
#define TW  64
#define TH  8

__global__ __launch_bounds__(128) void conv3_relu(
    const float* __restrict__ xin, int which,
    const float* __restrict__ wt, const float* __restrict__ bias)
{
    __shared__ float wsh[C * 9 * OCB];                       // 36864 B  [ic][k][oc16]
    __shared__ __align__(16) float xs[ICB * (TH + 2) * 68];  // 5440 B

    const int tid = threadIdx.x;
    const int bx  = blockIdx.x & 3;        // W tiles: 256/64
    const int by  = blockIdx.x >> 2;       // H tiles: 128/8
    const int oc0 = blockIdx.y * OCB;
    const int b   = blockIdx.z;

    const float* __restrict__ x = which ? g_aux  : xin;
    float*       __restrict__ y = which ? g_maux : g_main;

    // stage weights for this oc-group: layout [(ic*9 + k)*16 + o]
    for (int t = tid; t < C * 9 * OCB; t += 128) {
        int o  = t & 15;
        int k  = (t >> 4) % 9;
        int ic = t / (9 * OCB);
        wsh[t] = wt[((oc0 + o) * C + ic) * 9 + k];
    }

    const int tx = tid & 15;    // 16 -> 4 px each = 64 W
    const int ty = tid >> 4;    // 8 rows
    const float* xb = x + (size_t)b * C * HW;

    u64 acc[4][8];
    #pragma unroll
    for (int j = 0; j < 8; j++) {
        u64 bz = pack2(bias[oc0 + 2*j], bias[oc0 + 2*j + 1]);
        #pragma unroll
        for (int p = 0; p < 4; p++) acc[p][j] = bz;
    }

    for (int c0 = 0; c0 < C; c0 += ICB) {
        __syncthreads();
        // input tile with halo: 2 ic x 10 rows x 66 cols (padded stride 68)
        for (int t = tid; t < ICB * (TH + 2) * 66; t += 128) {
            int cc = t % 66;
            int rr = (t / 66) % (TH + 2);
            int ic = t / (66 * (TH + 2));
            int gy = by * TH - 1 + rr;
            int gx = bx * TW - 1 + cc;
            float v = 0.f;
            if ((unsigned)gy < H && (unsigned)gx < W)
                v = xb[(size_t)(c0 + ic) * HW + gy * W + gx];
            xs[(ic * (TH + 2) + rr) * 68 + cc] = v;
        }
        __syncthreads();

        #pragma unroll
        for (int ic = 0; ic < ICB; ic++) {
            #pragma unroll
            for (int ky = 0; ky < 3; ky++) {
                const float* row = &xs[(ic * (TH + 2) + ty + ky) * 68 + tx * 4];
                float4 v4 = *(const float4*)row;
                float w4 = row[4], w5 = row[5];
                u64 iv[6];
                iv[0] = pack2(v4.x, v4.x);
                iv[1] = pack2(v4.y, v4.y);
                iv[2] = pack2(v4.z, v4.z);
                iv[3] = pack2(v4.w, v4.w);
                iv[4] = pack2(w4, w4);
                iv[5] = pack2(w5, w5);
                const u64* wr = (const u64*)&wsh[((c0 + ic) * 9 + ky * 3) * OCB];
                #pragma unroll
                for (int kx = 0; kx < 3; kx++) {
                    #pragma unroll
                    for (int j = 0; j < 8; j++) {
                        u64 wv = wr[kx * 8 + j];
                        #pragma unroll
                        for (int p = 0; p < 4; p++)
                            ffma2(acc[p][j], iv[p + kx], wv);
                    }
                }
            }
        }
    }

    const int oy = by * TH + ty;
    const int ox = bx * TW + tx * 4;
    float* yb = y + (((size_t)b * C + oc0) * H + oy) * W + ox;
    #pragma unroll
    for (int j = 0; j < 8; j++) {
        float2 r0 = unpack2(acc[0][j]);
        float2 r1 = unpack2(acc[1][j]);
        float2 r2 = unpack2(acc[2][j]);
        float2 r3 = unpack2(acc[3][j]);
        float4 lo = make_float4(fmaxf(r0.x,0.f), fmaxf(r1.x,0.f), fmaxf(r2.x,0.f), fmaxf(r3.x,0.f));
        float4 hi = make_float4(fmaxf(r0.y,0.f), fmaxf(r1.y,0.f), fmaxf(r2.y,0.f), fmaxf(r3.y,0.f));
        *(float4*)(yb + (size_t)(2*j    ) * HW) = lo;
        *(float4*)(yb + (size_t)(2*j + 1) * HW) = hi;
    }
}

// ---------------- 4) 1x1 mask conv + sigmoid + blend ----------------
__global__ __launch_bounds__(256) void mask_out_kernel(
    const float* __restrict__ m, const float* __restrict__ wm,
    const float* __restrict__ bm, float* __restrict__ out)
{
    __shared__ float ws[128];
    if (threadIdx.x < 128) ws[threadIdx.x] = wm[threadIdx.x];
    __syncthreads();
    int idx = blockIdx.x * 256 + threadIdx.x;   // b*HW + p
    int p = idx & (HW - 1);
    int b = idx >> 15;
    const float* pm = g_main + ((size_t)b << 21) + p;
    const float* pa = g_maux + ((size_t)b << 21) + p;
    float s = bm[0];
    #pragma unroll
    for (int c = 0; c < 64; c++)
        s += ws[c] * pm[c << 15] + ws[64 + c] * pa[c << 15];
    float mk = 1.f / (1.f + expf(-s));
    const float* pmm = m + ((size_t)b << 21) + p;
    float* po = out + ((size_t)b << 21) + p;
    #pragma unroll
    for (int c = 0; c < 64; c++)
        po[c << 15] = pmm[c << 15] + mk * pa[c << 15];
}

// ---------------- launch ----------------
extern "C" void kernel_launch(void* const* d_in, const int* in_sizes, int n_in,
                              void* d_out, int out_size)
{
    const float* m  = (const float*)d_in[0];
    const float* f  = (const float*)d_in[1];
    const float* r  = (const float*)d_in[2];
    const float* bb = (const float*)d_in[3];
    const float* l  = (const float*)d_in[4];
    const float* u  = (const float*)d_in[5];
    const float* d  = (const float*)d_in[6];
    const float* wf = (const float*)d_in[7];
    const float* bf = (const float*)d_in[8];
    const float* wm = (const float*)d_in[9];
    const float* bm = (const float*)d_in[10];
    float* out = (float*)d_out;

    geom_kernel<<<128, 256>>>();
    gather_kernel<<<4 * C * HW / 256, 256>>>(bb, d, f, l, r, u);
    dim3 cgrid(64, 4, 4);                 // (bx,by) x oc-groups x batch
    conv3_relu<<<cgrid, 128>>>(m, 0, wf, bf);        // m -> g_main
    conv3_relu<<<cgrid, 128>>>(nullptr, 1, wf, bf);  // aux -> g_maux
    mask_out_kernel<<<4 * HW / 256, 256>>>(m, wm, bm, out);
}